// round 6
// baseline (speedup 1.0000x reference)
#include <cuda_runtime.h>
#include <math.h>

// Problem constants
#define S_LEN 2048
#define D_DIM 64
#define F_DIM 16
#define NTOK  16384      // B*S = 8*2048
#define DIN   2112       // D + 2*D*F
#define NOUT  128        // O gate + O proj
#define NITER 66         // DIN/32
#define TILE_T 128       // tokens per CTA

// ---------------- device scratch (static, allocation-free) ----------------
__device__ float g_f[D_DIM * F_DIM];          // freq_matrix * freq_scale
__device__ float g_walpha[4 * D_DIM];         // [h][d] folded alpha weights (incl 1/sqrt(8))
__device__ float g_calpha[4];                 // alpha bias
__device__ float g_ball[NOUT];                // bg | bp
__device__ float g_Wpack[DIN * NOUT];         // [k][og][g(2og),g(2og+1),p(2og),p(2og+1)]
__device__ float g_trig[S_LEN * D_DIM * 32];  // [s][d][ sin(16) | cos(16) ]

// ---------------- f32x2 helpers (packed dual fp32 FMA, sm_100+) ----------------
__device__ __forceinline__ unsigned long long pack2(float lo, float hi) {
    unsigned long long r;
    asm("mov.b64 %0, {%1, %2};" : "=l"(r) : "f"(lo), "f"(hi));
    return r;
}
__device__ __forceinline__ void unpack2(unsigned long long v, float& lo, float& hi) {
    asm("mov.b64 {%0, %1}, %2;" : "=f"(lo), "=f"(hi) : "l"(v));
}
__device__ __forceinline__ unsigned long long ffma2(unsigned long long a,
                                                    unsigned long long b,
                                                    unsigned long long c) {
    unsigned long long d;
    asm("fma.rn.f32x2 %0, %1, %2, %3;" : "=l"(d) : "l"(a), "l"(b), "l"(c));
    return d;
}

// Column permutation: token tau -> column so that 16 lanes (tg=0..15) reading
// their 4-token 16B chunk form two dense 128B lines (conflict-free LDS.128).
__device__ __forceinline__ int pcol(int t) {
    return ((t & 4) << 4) + ((t >> 3) << 2) + (t & 3);
}

// ---------------- kernel 0: fold tiny weights (1 block) ----------------
__global__ void precompute_small(const float* __restrict__ fm, const float* __restrict__ fs,
                                 const float* __restrict__ Wq, const float* __restrict__ bq,
                                 const float* __restrict__ Wk1,
                                 const float* __restrict__ Wqi, const float* __restrict__ bqi,
                                 const float* __restrict__ Wki,
                                 const float* __restrict__ bg, const float* __restrict__ bp) {
    __shared__ float sWcomb[32 * 64];  // Wqi @ Wq
    __shared__ float sb[32];           // Wqi @ bq + bqi
    __shared__ float su[32];           // Wki @ Wk1
    int tid = threadIdx.x;  // 256

    for (int i = tid; i < D_DIM * F_DIM; i += 256) g_f[i] = fm[i] * fs[i];

    for (int i = tid; i < 2048; i += 256) {
        int e = i >> 6, d = i & 63;
        float s = 0.f;
        #pragma unroll 8
        for (int a = 0; a < 32; a++) s += Wqi[e * 32 + a] * Wq[a * 64 + d];
        sWcomb[e * 64 + d] = s;
    }
    if (tid < 32) {
        float s = 0.f, uu = 0.f;
        for (int a = 0; a < 32; a++) {
            s += Wqi[tid * 32 + a] * bq[a];
            uu += Wki[tid * 32 + a] * Wk1[a];
        }
        sb[tid] = s + bqi[tid];
        su[tid] = uu;
    }
    if (tid < NOUT) g_ball[tid] = (tid < 64) ? bg[tid] : bp[tid - 64];
    __syncthreads();

    const float rs8 = 0.35355339059327373f;  // 1/sqrt(8)
    {
        int h = tid >> 6, d = tid & 63;  // 4*64 = 256 exactly
        float s = 0.f;
        #pragma unroll
        for (int e = 0; e < 8; e++) s += sWcomb[(h * 8 + e) * 64 + d] * su[h * 8 + e];
        g_walpha[h * 64 + d] = s * rs8;
    }
    if (tid < 4) {
        float s = 0.f;
        #pragma unroll
        for (int e = 0; e < 8; e++) s += sb[tid * 8 + e] * su[tid * 8 + e];
        g_calpha[tid] = s * rs8;
    }
}

// ---------------- kernel 1: pack Wg|Wp into [k][og][g,g,p,p] layout ----------------
__global__ void pack_weights(const float* __restrict__ Wg, const float* __restrict__ Wp) {
    int i = blockIdx.x * blockDim.x + threadIdx.x;
    if (i >= DIN * NOUT) return;
    int k = i >> 7, c = i & 127;
    int og = c >> 2, j = c & 3;
    int o = 2 * og + (j & 1);
    g_Wpack[i] = (j < 2) ? Wg[(size_t)o * DIN + k] : Wp[(size_t)o * DIN + k];
}

// ---------------- kernel 2: trig table [s][d][sin16|cos16] ----------------
__global__ void trig_table(const float* __restrict__ phase) {
    int i = blockIdx.x * blockDim.x + threadIdx.x;  // S*D*F = 2M
    if (i >= S_LEN * D_DIM * F_DIM) return;
    int f = i & 15, d = (i >> 4) & 63, s = i >> 10;
    float t = (float)s * (1.0f / (float)(S_LEN - 1));
    float sig = 6.283185307179586f * t * g_f[d * 16 + f] + phase[d * 16 + f];
    float sv, cv;
    sincosf(sig, &sv, &cv);
    size_t base = ((size_t)s * 64 + d) * 32;
    g_trig[base + f] = sv;
    g_trig[base + 16 + f] = cv;
}

// ---------------- kernel 3: fused feature + GEMM + gating ----------------
// grid = 128 CTAs (one per SM), 512 threads (16 warps, 4/SMSP for latency hiding).
// CTA tile: 128 tokens x 128 outputs. Thread tile: 8 tokens x (2 gate + 2 proj).
__global__ void __launch_bounds__(512, 1)
fused_main(const float* __restrict__ x, float* __restrict__ out) {
    __shared__ __align__(16) float xs[64 * 128];  // 32KB [d][pcol(t)]; rows 0-31 reused as As
    __shared__ __align__(16) float Ws[32 * 128];  // 16KB [k][og*4]
    float* As = xs;  // alias: feature chunk overwrites x rows 0-31 (consumed in iter 0)

    int tid = threadIdx.x;
    int tokBase = blockIdx.x * TILE_T;
    int sBase = tokBase & (S_LEN - 1);  // 2048 % 128 == 0: tile within one sequence
    const float* xb = x + (size_t)tokBase * 64;

    // ---- load x tile, transpose into [d][pcol(t)]: 2048 float4 total ----
    #pragma unroll
    for (int r = 0; r < 4; r++) {
        int i = tid + 512 * r;
        float4 v = ((const float4*)xb)[i];
        int tau = i >> 4, d0 = (i & 15) << 2;
        int pc = pcol(tau);
        xs[(d0 + 0) * 128 + pc] = v.x;
        xs[(d0 + 1) * 128 + pc] = v.y;
        xs[(d0 + 2) * 128 + pc] = v.z;
        xs[(d0 + 3) * 128 + pc] = v.w;
    }
    __syncthreads();

    // ---- per-thread alpha: thread = (token taua, head hh); lanes 4q..4q+3 = heads of token
    int taua = tid >> 2, hh = tid & 3;
    int pca = pcol(taua);
    float aval = __ldg(&g_calpha[hh]);
    {
        const float* wa = g_walpha + hh * 64;
        #pragma unroll 8
        for (int d = 0; d < 64; d++)
            aval = fmaf(xs[d * 128 + pca], __ldg(wa + d), aval);
    }

    // ---- GEMM mapping: warp w covers og {2w, 2w+1}; lanes 0-15 og=2w, 16-31 og=2w+1
    int lane = tid & 31, w = tid >> 5;
    int og = 2 * w + (lane >> 4);   // 0..31, outputs {2og, 2og+1}
    int tg = lane & 15;
    int t0 = tg * 8;

    // accumulators: [oi][token-pair], f32x2 packs two adjacent tokens
    unsigned long long accG[2][4], accP[2][4];
    #pragma unroll
    for (int oi = 0; oi < 2; oi++) {
        float bgv = __ldg(&g_ball[2 * og + oi]);
        float bpv = __ldg(&g_ball[64 + 2 * og + oi]);
        unsigned long long pg = pack2(bgv, bgv), pp = pack2(bpv, bpv);
        #pragma unroll
        for (int p = 0; p < 4; p++) { accG[oi][p] = pg; accP[oi][p] = pp; }
    }

    // prefetch weight chunk 0 (16KB / 512 threads = 2 float4 each)
    float4 pre[2];
    {
        const float4* ws = (const float4*)g_Wpack;
        pre[0] = __ldg(ws + tid);
        pre[1] = __ldg(ws + tid + 512);
    }

    float vv[8];      // attention weights (head-summed) for this thread's 8 feature rows
    float4 tpre[2];   // prefetched trig values for rows hh*8 .. hh*8+7

    for (int iter = 0; iter < NITER; iter++) {
        __syncthreads();  // previous GEMM done reading As/Ws

        // commit prefetched weights to smem
        ((float4*)Ws)[tid] = pre[0];
        ((float4*)Ws)[tid + 512] = pre[1];

        const float* Aptr;
        if (iter < 2) {
            Aptr = xs + iter * 32 * 128;  // raw x rows
        } else {
            // write fourier features for d=iter-2: rows hh*8 .. +7, column pca
            float* dst = As + (hh * 8) * 128 + pca;
            const float* tp = (const float*)tpre;
            #pragma unroll
            for (int j = 0; j < 8; j++) dst[j * 128] = tp[j] * vv[j];
            Aptr = As;
        }
        __syncthreads();

        // prefetch next weight chunk (overlaps GEMM)
        if (iter + 1 < NITER) {
            const float4* ws = (const float4*)(g_Wpack + (size_t)(iter + 1) * 32 * NOUT);
            pre[0] = __ldg(ws + tid);
            pre[1] = __ldg(ws + tid + 512);
        }

        // softmax + trig prefetch for NEXT iter's produce (d_next = iter-1); no sync
        // between here and the GEMM below -> MUFU/LDG overlap FMA across warps.
        if (iter >= 1 && iter <= 64) {
            int dn = iter - 1;
            const float4* tb = (const float4*)(g_trig +
                ((size_t)(sBase + taua) * 64 + dn) * 32 + hh * 8);
            tpre[0] = __ldg(tb);
            tpre[1] = __ldg(tb + 1);

            const float4* fv4 = (const float4*)(g_f + dn * 16);
            float pr[16];
            float m = -1e30f;
            #pragma unroll
            for (int q = 0; q < 4; q++) {
                float4 fr = __ldg(fv4 + q);
                pr[4 * q + 0] = fr.x * aval;
                pr[4 * q + 1] = fr.y * aval;
                pr[4 * q + 2] = fr.z * aval;
                pr[4 * q + 3] = fr.w * aval;
            }
            #pragma unroll
            for (int f_ = 0; f_ < 16; f_++) m = fmaxf(m, pr[f_]);
            float ss = 0.f;
            #pragma unroll
            for (int f_ = 0; f_ < 16; f_++) {
                pr[f_] = __expf(pr[f_] - m);
                ss += pr[f_];
            }
            float inv = 0.25f / ss;  // head-average folded in
            int base = (hh & 1) * 8; // this thread needs aw[f] for f in [base, base+8)
            #pragma unroll
            for (int f_ = 0; f_ < 16; f_++) {
                float v = pr[f_] * inv;
                v += __shfl_xor_sync(0xFFFFFFFFu, v, 1);  // sum 4 heads within token quad
                v += __shfl_xor_sync(0xFFFFFFFFu, v, 2);
                if ((f_ & 8) == base) vv[f_ & 7] = v;
            }
        }

        // ---- GEMM: 32 rank-1 updates, 16 FFMA2 per thread per k ----
        #pragma unroll 8
        for (int k = 0; k < 32; k++) {
            ulonglong2 alo = *(const ulonglong2*)(Aptr + k * 128 + tg * 4);       // tok t0..t0+3
            ulonglong2 ahi = *(const ulonglong2*)(Aptr + k * 128 + 64 + tg * 4);  // tok t0+4..7
            float4 w4 = *(const float4*)(Ws + k * 128 + og * 4);  // {g0,g1,p0,p1} broadcast
            unsigned long long g0 = pack2(w4.x, w4.x), g1 = pack2(w4.y, w4.y);
            unsigned long long p0 = pack2(w4.z, w4.z), p1 = pack2(w4.w, w4.w);
            accG[0][0] = ffma2(alo.x, g0, accG[0][0]); accG[0][1] = ffma2(alo.y, g0, accG[0][1]);
            accG[0][2] = ffma2(ahi.x, g0, accG[0][2]); accG[0][3] = ffma2(ahi.y, g0, accG[0][3]);
            accG[1][0] = ffma2(alo.x, g1, accG[1][0]); accG[1][1] = ffma2(alo.y, g1, accG[1][1]);
            accG[1][2] = ffma2(ahi.x, g1, accG[1][2]); accG[1][3] = ffma2(ahi.y, g1, accG[1][3]);
            accP[0][0] = ffma2(alo.x, p0, accP[0][0]); accP[0][1] = ffma2(alo.y, p0, accP[0][1]);
            accP[0][2] = ffma2(ahi.x, p0, accP[0][2]); accP[0][3] = ffma2(ahi.y, p0, accP[0][3]);
            accP[1][0] = ffma2(alo.x, p1, accP[1][0]); accP[1][1] = ffma2(alo.y, p1, accP[1][1]);
            accP[1][2] = ffma2(ahi.x, p1, accP[1][2]); accP[1][3] = ffma2(ahi.y, p1, accP[1][3]);
        }
    }

    // ---- epilogue: gate/proj live in same thread; add residual (x reloaded from L2) ----
    #pragma unroll
    for (int p = 0; p < 4; p++) {
        float gl[2], gh[2], pl[2], ph[2];
        #pragma unroll
        for (int oi = 0; oi < 2; oi++) {
            unpack2(accG[oi][p], gl[oi], gh[oi]);
            unpack2(accP[oi][p], pl[oi], ph[oi]);
        }
        #pragma unroll
        for (int half = 0; half < 2; half++) {
            int tau = t0 + 2 * p + half;
            const float* xr = x + (size_t)(tokBase + tau) * 64 + 2 * og;
            float2 xv = __ldg((const float2*)xr);
            float2 ov;
            float g, pv;
            g = half ? gh[0] : gl[0]; pv = half ? ph[0] : pl[0];
            ov.x = xv.x + __frcp_rn(1.f + __expf(-g)) * (pv * __frcp_rn(1.f + __expf(-pv)));
            g = half ? gh[1] : gl[1]; pv = half ? ph[1] : pl[1];
            ov.y = xv.y + __frcp_rn(1.f + __expf(-g)) * (pv * __frcp_rn(1.f + __expf(-pv)));
            *((float2*)(out + (size_t)(tokBase + tau) * 64 + 2 * og)) = ov;
        }
    }
}

// ---------------- launch ----------------
extern "C" void kernel_launch(void* const* d_in, const int* in_sizes, int n_in,
                              void* d_out, int out_size) {
    const float* x     = (const float*)d_in[0];
    const float* fm    = (const float*)d_in[1];
    const float* phase = (const float*)d_in[2];
    const float* fsc   = (const float*)d_in[3];
    const float* Wq    = (const float*)d_in[4];
    const float* bq    = (const float*)d_in[5];
    const float* Wk1   = (const float*)d_in[6];
    // d_in[7] = bk1: constant along softmax axis -> cancels
    const float* Wqi   = (const float*)d_in[8];
    const float* bqi   = (const float*)d_in[9];
    const float* Wki   = (const float*)d_in[10];
    // d_in[11] = bki: cancels in softmax
    const float* Wg    = (const float*)d_in[12];
    const float* bg    = (const float*)d_in[13];
    const float* Wp    = (const float*)d_in[14];
    const float* bp    = (const float*)d_in[15];
    float* out = (float*)d_out;

    precompute_small<<<1, 256>>>(fm, fsc, Wq, bq, Wk1, Wqi, bqi, Wki, bg, bp);
    pack_weights<<<(DIN * NOUT + 255) / 256, 256>>>(Wg, Wp);
    trig_table<<<(S_LEN * D_DIM * F_DIM + 255) / 256, 256>>>(phase);
    fused_main<<<NTOK / TILE_T, 512>>>(x, out);
}

// round 13
// speedup vs baseline: 2.5326x; 2.5326x over previous
#include <cuda_runtime.h>
#include <cuda_fp16.h>
#include <math.h>

// Problem constants
#define S_LEN 2048
#define D_DIM 64
#define F_DIM 16
#define NTOK  16384      // B*S
#define DIN   2112       // D + 2*D*F
#define NCH   33         // K chunks of 64
#define TILE_T 128       // tokens per CTA

// ---------------- device scratch ----------------
__device__ float g_f[D_DIM * F_DIM];          // freq_matrix * freq_scale
__device__ float g_walpha[4 * D_DIM];         // [h][d] folded alpha weights (incl 1/sqrt(8))
__device__ float g_calpha[4];                 // alpha bias
__device__ __half g_Wh[128 * DIN];            // [o][k] f16: rows 0-63 Wg, 64-127 Wp
__device__ float g_trig[S_LEN * D_DIM * 32];  // [s][d][ sin(16) | cos(16) ]

// ---------------- helpers ----------------
__device__ __forceinline__ unsigned smem_u32(const void* p) {
    unsigned a;
    asm("{ .reg .u64 t; cvta.to.shared.u64 t, %1; cvt.u32.u64 %0, t; }" : "=r"(a) : "l"(p));
    return a;
}
#define SWZ(o) ((o) ^ (((o) >> 3) & 0x70))

__device__ __forceinline__ void ldsm4(unsigned& r0, unsigned& r1, unsigned& r2, unsigned& r3,
                                      unsigned addr) {
    asm volatile("ldmatrix.sync.aligned.m8n8.x4.shared.b16 {%0,%1,%2,%3}, [%4];"
                 : "=r"(r0), "=r"(r1), "=r"(r2), "=r"(r3) : "r"(addr));
}
__device__ __forceinline__ void mma16816(float* c, unsigned a0, unsigned a1, unsigned a2,
                                         unsigned a3, unsigned b0, unsigned b1) {
    asm volatile(
        "mma.sync.aligned.m16n8k16.row.col.f32.f16.f16.f32 "
        "{%0,%1,%2,%3}, {%4,%5,%6,%7}, {%8,%9}, {%0,%1,%2,%3};"
        : "+f"(c[0]), "+f"(c[1]), "+f"(c[2]), "+f"(c[3])
        : "r"(a0), "r"(a1), "r"(a2), "r"(a3), "r"(b0), "r"(b1));
}

// ---------------- kernel 0: fold tiny weights (1 block, 256 thr) ----------------
__global__ void precompute_small(const float* __restrict__ fm, const float* __restrict__ fs,
                                 const float* __restrict__ Wq, const float* __restrict__ bq,
                                 const float* __restrict__ Wk1,
                                 const float* __restrict__ Wqi, const float* __restrict__ bqi,
                                 const float* __restrict__ Wki) {
    __shared__ float sWcomb[32 * 64];
    __shared__ float sb[32];
    __shared__ float su[32];
    int tid = threadIdx.x;

    for (int i = tid; i < D_DIM * F_DIM; i += 256) g_f[i] = fm[i] * fs[i];

    for (int i = tid; i < 2048; i += 256) {
        int e = i >> 6, d = i & 63;
        float s = 0.f;
        #pragma unroll 8
        for (int a = 0; a < 32; a++) s += Wqi[e * 32 + a] * Wq[a * 64 + d];
        sWcomb[e * 64 + d] = s;
    }
    if (tid < 32) {
        float s = 0.f, uu = 0.f;
        for (int a = 0; a < 32; a++) {
            s += Wqi[tid * 32 + a] * bq[a];
            uu += Wki[tid * 32 + a] * Wk1[a];
        }
        sb[tid] = s + bqi[tid];
        su[tid] = uu;
    }
    __syncthreads();

    const float rs8 = 0.35355339059327373f;  // 1/sqrt(8)
    {
        int h = tid >> 6, d = tid & 63;
        float s = 0.f;
        #pragma unroll
        for (int e = 0; e < 8; e++) s += sWcomb[(h * 8 + e) * 64 + d] * su[h * 8 + e];
        g_walpha[h * 64 + d] = s * rs8;
    }
    if (tid < 4) {
        float s = 0.f;
        #pragma unroll
        for (int e = 0; e < 8; e++) s += sb[tid * 8 + e] * su[tid * 8 + e];
        g_calpha[tid] = s * rs8;
    }
}

// ---------------- kernel 1: convert Wg|Wp to f16 [o][k] ----------------
__global__ void convert_wh(const float* __restrict__ Wg, const float* __restrict__ Wp) {
    int i = blockIdx.x * blockDim.x + threadIdx.x;
    if (i >= 128 * DIN) return;
    int o = i / DIN, k = i - o * DIN;
    float v = (o < 64) ? Wg[(size_t)o * DIN + k] : Wp[(size_t)(o - 64) * DIN + k];
    g_Wh[i] = __float2half_rn(v);
}

// ---------------- kernel 2: trig table [s][d][sin16|cos16] f32 ----------------
__global__ void trig_table(const float* __restrict__ phase) {
    int i = blockIdx.x * blockDim.x + threadIdx.x;
    if (i >= S_LEN * D_DIM * F_DIM) return;
    int f = i & 15, d = (i >> 4) & 63, s = i >> 10;
    float t = (float)s * (1.0f / (float)(S_LEN - 1));
    float sig = 6.283185307179586f * t * g_f[d * 16 + f] + phase[d * 16 + f];
    float sv, cv;
    sincosf(sig, &sv, &cv);
    size_t base = ((size_t)s * 64 + d) * 32;
    g_trig[base + f] = sv;
    g_trig[base + 16 + f] = cv;
}

// ---------------- kernel 3: fused feature + HMMA GEMM + gating ----------------
// 128 CTAs x 512 threads (16 warps). CTA tile: 128 tok x 128 out, K = 33 chunks of 64.
// A tile [128 tok][64 k] f16 SW128 (16KB), B tile [128 out][64 k] f16 SW128 (16KB).
// Warp tile m16 x n64 via mma.sync.m16n8k16 (f16 in, f32 acc). Warps 0-7: gate outs,
// warps 8-15: proj outs (same tokens); epilogue swaps proj preacts through smem.
// B fragments via NON-trans ldmatrix: smem [n][k] is col-major KxN, so lane l's
// row-n address yields exactly b = B[k=2(l%4)][n=l/4] as mma.row.col requires.
__global__ void __launch_bounds__(512, 1)
fused_hmma(const float* __restrict__ x, const float* __restrict__ bg,
           const float* __restrict__ bp, float* __restrict__ out) {
    __shared__ __align__(1024) char sm[32768];
    const unsigned SM_A = 0, SM_B = 16384;
    unsigned smb = smem_u32(sm);

    int tid = threadIdx.x, wid = tid >> 5, lane = tid & 31;
    int tokBase = blockIdx.x * TILE_T;
    int sBase = tokBase & (S_LEN - 1);  // tile lies within one sequence (2048 % 128 == 0)

    int tau = tid >> 2, hh = tid & 3;

    // ---- alpha for head hh of token tau; capture x segment hh for chunk-0 A ----
    float aval = __ldg(&g_calpha[hh]);
    float4 xseg[4];
    {
        const float4* xr = (const float4*)(x + (size_t)(tokBase + tau) * 64);
        const float4* wa = (const float4*)(g_walpha + hh * 64);
        #pragma unroll
        for (int q = 0; q < 16; q++) {
            float4 xv = __ldg(xr + q);
            float4 wv = __ldg(wa + q);
            aval += xv.x * wv.x + xv.y * wv.y + xv.z * wv.z + xv.w * wv.w;
            if ((q >> 2) == hh) xseg[q & 3] = xv;
        }
    }

    // ---- chunk-0 A tile: x -> f16, swizzled ----
    {
        unsigned o0 = (unsigned)(tau * 128 + hh * 32);
        uint4 pay[2];
        __half2* ph = (__half2*)pay;
        #pragma unroll
        for (int j = 0; j < 4; j++) {
            ph[2 * j]     = __floats2half2_rn(xseg[j].x, xseg[j].y);
            ph[2 * j + 1] = __floats2half2_rn(xseg[j].z, xseg[j].w);
        }
        *(uint4*)(sm + SM_A + SWZ(o0)) = pay[0];
        *(uint4*)(sm + SM_A + SWZ(o0 + 16)) = pay[1];
    }

    // ---- B chunk-0 prefetch registers ----
    int br = tid >> 2, bs = tid & 3;  // weight row (0..127), 32B segment
    const __half* bgp = g_Wh + (size_t)br * DIN + bs * 16;
    unsigned bso0 = (unsigned)(br * 128 + bs * 32);
    uint4 bpre0 = *(const uint4*)bgp;
    uint4 bpre1 = *(const uint4*)(bgp + 8);

    // ---- HMMA mapping ----
    int m0 = (wid & 7) * 16;          // token rows of this warp
    int N0 = (wid >> 3) * 64;         // 0 = gate outputs, 64 = proj outputs
    int i0 = lane & 7, grp = lane >> 3;
    // A (x4): mat0 rows m0..+7 k0-7 | mat1 rows m0+8..+15 k0-7 | mat2/3 same rows k8-15
    unsigned aRowB = (unsigned)((m0 + i0 + (grp & 1) * 8) * 128);
    unsigned aKadd = (unsigned)((grp >> 1) * 16);
    // B (x4, non-trans): mat0 n0-7 k0-7 (b0) | mat1 n0-7 k8-15 (b1) | mat2/3 n8-15 (next n8)
    unsigned bRowB = (unsigned)((N0 + i0 + (grp >> 1) * 8) * 128);
    unsigned bKadd = (unsigned)((grp & 1) * 16);

    float acc[8][4];  // [n8 block][frag]; biases added in epilogue
    #pragma unroll
    for (int nb = 0; nb < 8; nb++)
        #pragma unroll
        for (int j = 0; j < 4; j++) acc[nb][j] = 0.f;

    int base = (hh & 1) * 8;  // aw indices this thread needs for produce
    uint4 fpay[2];

    for (int c = 0; c < NCH; c++) {
        __syncthreads();  // previous chunk's mma done reading A/B

        // commit weight chunk c; commit feature chunk c (produced last iter)
        *(uint4*)(sm + SM_B + SWZ(bso0)) = bpre0;
        *(uint4*)(sm + SM_B + SWZ(bso0 + 16)) = bpre1;
        if (c > 0) {
            *(uint4*)(sm + SM_A + SWZ((unsigned)(tau * 128 + hh * 16))) = fpay[0];
            *(uint4*)(sm + SM_A + SWZ((unsigned)(tau * 128 + 64 + hh * 16))) = fpay[1];
        }
        __syncthreads();

        bool more = (c + 1 < NCH);
        if (more) {
            // prefetch weight chunk c+1
            bpre0 = *(const uint4*)(bgp + (size_t)(c + 1) * 64);
            bpre1 = *(const uint4*)(bgp + (size_t)(c + 1) * 64 + 8);

            // produce features for chunk c+1 (d = 2c, 2c+1) — overlaps mma below
            #pragma unroll
            for (int dl = 0; dl < 2; dl++) {
                int d = 2 * c + dl;
                const float4* tb = (const float4*)(g_trig +
                    ((size_t)(sBase + tau) * 64 + d) * 32 + hh * 8);
                float4 t0 = __ldg(tb), t1 = __ldg(tb + 1);

                const float4* fv4 = (const float4*)(g_f + d * 16);
                float pr[16];
                float m = -1e30f;
                #pragma unroll
                for (int q = 0; q < 4; q++) {
                    float4 fr = __ldg(fv4 + q);
                    pr[4 * q + 0] = fr.x * aval;
                    pr[4 * q + 1] = fr.y * aval;
                    pr[4 * q + 2] = fr.z * aval;
                    pr[4 * q + 3] = fr.w * aval;
                }
                #pragma unroll
                for (int f_ = 0; f_ < 16; f_++) m = fmaxf(m, pr[f_]);
                float ss = 0.f;
                #pragma unroll
                for (int f_ = 0; f_ < 16; f_++) {
                    pr[f_] = __expf(pr[f_] - m);
                    ss += pr[f_];
                }
                float inv = 0.25f / ss;  // head average folded in
                float vv[8];
                #pragma unroll
                for (int f_ = 0; f_ < 16; f_++) {
                    float v = pr[f_] * inv;
                    v += __shfl_xor_sync(0xFFFFFFFFu, v, 1);  // sum over 4 heads
                    v += __shfl_xor_sync(0xFFFFFFFFu, v, 2);
                    if ((f_ & 8) == base) vv[f_ & 7] = v;
                }
                __half2* fh = (__half2*)&fpay[dl];
                fh[0] = __floats2half2_rn(t0.x * vv[0], t0.y * vv[1]);
                fh[1] = __floats2half2_rn(t0.z * vv[2], t0.w * vv[3]);
                fh[2] = __floats2half2_rn(t1.x * vv[4], t1.y * vv[5]);
                fh[3] = __floats2half2_rn(t1.z * vv[6], t1.w * vv[7]);
            }
        }

        // ---- HMMA: 4 k16 steps x 8 n8 blocks ----
        #pragma unroll
        for (int ks = 0; ks < 4; ks++) {
            unsigned a0, a1, a2, a3;
            ldsm4(a0, a1, a2, a3, smb + SM_A + SWZ(aRowB + aKadd + ks * 32));
            #pragma unroll
            for (int nb2 = 0; nb2 < 4; nb2++) {
                unsigned b0, b1, b2, b3;
                ldsm4(b0, b1, b2, b3,
                      smb + SM_B + SWZ(bRowB + nb2 * 2048 + bKadd + ks * 32));
                mma16816(acc[nb2 * 2], a0, a1, a2, a3, b0, b1);
                mma16816(acc[nb2 * 2 + 1], a0, a1, a2, a3, b2, b3);
            }
        }
    }

    // ---- epilogue ----
    // Fragment c[nb]: rows m0 + gr and m0 + gr + 8; cols nb*8 + qc + {0,1}
    int gr = lane >> 2, qc = (lane & 3) * 2;
    float* smF = (float*)sm;  // [128 tok][64 out] proj preacts (reuses A|B tiles)

    __syncthreads();  // all mma reads of smem done before overwrite
    if (N0 == 64) {   // proj warps: stash preacts
        #pragma unroll
        for (int nb = 0; nb < 8; nb++) {
            int o = nb * 8 + qc;
            *(float2*)(smF + (m0 + gr) * 64 + o)     = make_float2(acc[nb][0], acc[nb][1]);
            *(float2*)(smF + (m0 + gr + 8) * 64 + o) = make_float2(acc[nb][2], acc[nb][3]);
        }
    }
    __syncthreads();
    if (N0 == 0) {    // gate warps: combine + residual + store
        #pragma unroll
        for (int nb = 0; nb < 8; nb++) {
            int o = nb * 8 + qc;
            float2 bgv = *(const float2*)(bg + o);
            float2 bpv = *(const float2*)(bp + o);
            #pragma unroll
            for (int half = 0; half < 2; half++) {
                int tl = m0 + gr + half * 8;
                int tok = tokBase + tl;
                float gv0 = acc[nb][2 * half]     + bgv.x;
                float gv1 = acc[nb][2 * half + 1] + bgv.y;
                float2 pv = *(const float2*)(smF + tl * 64 + o);
                pv.x += bpv.x; pv.y += bpv.y;
                float2 xv = __ldg((const float2*)(x + (size_t)tok * 64 + o));
                float2 ov;
                ov.x = xv.x + __frcp_rn(1.f + __expf(-gv0)) *
                              (pv.x * __frcp_rn(1.f + __expf(-pv.x)));
                ov.y = xv.y + __frcp_rn(1.f + __expf(-gv1)) *
                              (pv.y * __frcp_rn(1.f + __expf(-pv.y)));
                *(float2*)(out + (size_t)tok * 64 + o) = ov;
            }
        }
    }
}

// ---------------- launch ----------------
extern "C" void kernel_launch(void* const* d_in, const int* in_sizes, int n_in,
                              void* d_out, int out_size) {
    const float* x     = (const float*)d_in[0];
    const float* fm    = (const float*)d_in[1];
    const float* phase = (const float*)d_in[2];
    const float* fsc   = (const float*)d_in[3];
    const float* Wq    = (const float*)d_in[4];
    const float* bq    = (const float*)d_in[5];
    const float* Wk1   = (const float*)d_in[6];
    // d_in[7] = bk1: constant along softmax axis -> cancels
    const float* Wqi   = (const float*)d_in[8];
    const float* bqi   = (const float*)d_in[9];
    const float* Wki   = (const float*)d_in[10];
    // d_in[11] = bki: cancels in softmax
    const float* Wg    = (const float*)d_in[12];
    const float* bg    = (const float*)d_in[13];
    const float* Wp    = (const float*)d_in[14];
    const float* bp    = (const float*)d_in[15];
    float* out = (float*)d_out;

    precompute_small<<<1, 256>>>(fm, fsc, Wq, bq, Wk1, Wqi, bqi, Wki);
    convert_wh<<<(128 * DIN + 255) / 256, 256>>>(Wg, Wp);
    trig_table<<<(S_LEN * D_DIM * F_DIM + 255) / 256, 256>>>(phase);
    fused_hmma<<<NTOK / TILE_T, 512>>>(x, bg, bp, out);
}